// round 14
// baseline (speedup 1.0000x reference)
#include <cuda_runtime.h>
#include <cuda_bf16.h>

// LIF neuron scan:
//   u[t] = tau * u[t-1] + x[t];  o[t] = (u[t] > 1);  u[t] *= (1 - o[t])
// x: [B, T, N] fp32, out: [B, T, N] fp32.  B=32, T=32, N=65536.
//
// R14: hybrid LDG + cp.async split. Chunk 0 = 16-deep LDG register burst
// (R6 pattern); chunk 1 = 16-deep cp.async group into 32KB smem. Both fired
// up front -> all 32 loads outstanding (same as R11, our best at 84.4us),
// but footprint halves on both axes: smem 64->32KB, regs ~154->~95 (chunk 1
// holds ZERO registers in flight). __launch_bounds__(128,4) -> 4 blocks/SM
// = 16 warps (R6's best-measured warp count) vs R11's 12, at identical
// burst/in-flight structure. Store runs stay pure 16-deep STG bursts (R9);
// no __syncthreads (each thread consumes only its own cp.async data; R13's
// 8-deep groups regressed, so groups stay 16-deep).

#define T_STEPS 32
#define B_BATCH 32
#define CHUNK   16
#define BLOCK   128

__device__ __forceinline__ void cp_async16(void* smem_dst, const void* gsrc, bool pred) {
    unsigned saddr = (unsigned)__cvta_generic_to_shared(smem_dst);
    if (pred)
        asm volatile("cp.async.cg.shared.global [%0], [%1], 16;\n"
                     :: "r"(saddr), "l"(gsrc));
}
__device__ __forceinline__ void cp_commit() {
    asm volatile("cp.async.commit_group;\n" ::: "memory");
}
template <int N>
__device__ __forceinline__ void cp_wait() {
    asm volatile("cp.async.wait_group %0;\n" :: "n"(N) : "memory");
}

__global__ __launch_bounds__(BLOCK, 4) void lif_scan_kernel(
    const float4* __restrict__ x,
    const float*  __restrict__ tau_p,
    float4*       __restrict__ out,
    int nv,          // N/4 (float4 lanes per (b,t) row)
    int total)       // B * nv
{
    extern __shared__ float4 sbuf[];   // [CHUNK][BLOCK] = 32 KB

    int tid = threadIdx.x;
    int i   = blockIdx.x * BLOCK + tid;
    bool active = (i < total);
    int  ii = active ? i : 0;

    // clamp learned decay to [0,1]
    float tau = __ldg(tau_p);
    tau = fminf(fmaxf(tau, 0.0f), 1.0f);

    int b = ii / nv;                   // nv is a power of two; compiler -> shift
    int j = ii - b * nv;

    size_t base = (size_t)b * T_STEPS * nv + j;
    const float4* xb = x   + base;
    float4*       ob = out + base;

    const size_t half = (size_t)CHUNK * nv;

    // ---- chunk 0: 16-deep LDG register burst ----
    float4 bufA[CHUNK];
#pragma unroll
    for (int t = 0; t < CHUNK; t++)
        bufA[t] = active ? __ldcs(&xb[(size_t)t * nv])
                         : make_float4(0.f, 0.f, 0.f, 0.f);

    // ---- chunk 1: 16-deep cp.async group (zero registers in flight) ----
#pragma unroll
    for (int t = 0; t < CHUNK; t++)
        cp_async16(&sbuf[t * BLOCK + tid], &xb[half + (size_t)t * nv], active);
    cp_commit();

    float ux = 0.0f, uy = 0.0f, uz = 0.0f, uw = 0.0f;

    // ---- compute A (overwrite bufA with outputs; chunk 1 in flight) ----
#pragma unroll
    for (int t = 0; t < CHUNK; t++) {
        float4 xi = bufA[t];

        ux = fmaf(tau, ux, xi.x);
        uy = fmaf(tau, uy, xi.y);
        uz = fmaf(tau, uz, xi.z);
        uw = fmaf(tau, uw, xi.w);

        float4 o;
        o.x = (ux > 1.0f) ? 1.0f : 0.0f;
        o.y = (uy > 1.0f) ? 1.0f : 0.0f;
        o.z = (uz > 1.0f) ? 1.0f : 0.0f;
        o.w = (uw > 1.0f) ? 1.0f : 0.0f;

        ux = (ux > 1.0f) ? 0.0f : ux;
        uy = (uy > 1.0f) ? 0.0f : uy;
        uz = (uz > 1.0f) ? 0.0f : uz;
        uw = (uw > 1.0f) ? 0.0f : uw;

        bufA[t] = o;
    }

    // ---- store run A: 16 back-to-back streaming stores ----
    if (active) {
#pragma unroll
        for (int t = 0; t < CHUNK; t++)
            __stcs(&ob[(size_t)t * nv], bufA[t]);
    }

    // ---- chunk 1 landed; compute B from smem into bufA ----
    cp_wait<0>();

#pragma unroll
    for (int t = 0; t < CHUNK; t++) {
        float4 xi = sbuf[t * BLOCK + tid];

        ux = fmaf(tau, ux, xi.x);
        uy = fmaf(tau, uy, xi.y);
        uz = fmaf(tau, uz, xi.z);
        uw = fmaf(tau, uw, xi.w);

        float4 o;
        o.x = (ux > 1.0f) ? 1.0f : 0.0f;
        o.y = (uy > 1.0f) ? 1.0f : 0.0f;
        o.z = (uz > 1.0f) ? 1.0f : 0.0f;
        o.w = (uw > 1.0f) ? 1.0f : 0.0f;

        ux = (ux > 1.0f) ? 0.0f : ux;
        uy = (uy > 1.0f) ? 0.0f : uy;
        uz = (uz > 1.0f) ? 0.0f : uz;
        uw = (uw > 1.0f) ? 0.0f : uw;

        bufA[t] = o;
    }

    // ---- store run B: 16 back-to-back streaming stores ----
    if (active) {
#pragma unroll
        for (int t = 0; t < CHUNK; t++)
            __stcs(&ob[half + (size_t)t * nv], bufA[t]);
    }
}

extern "C" void kernel_launch(void* const* d_in, const int* in_sizes, int n_in,
                              void* d_out, int out_size)
{
    const float* x   = (const float*)d_in[0];   // [B, T, N] fp32
    const float* tau = (const float*)d_in[1];   // [1] fp32

    int total_elems = in_sizes[0];                       // B*T*N
    int N  = total_elems / (B_BATCH * T_STEPS);
    int nv = N / 4;                                      // float4 per (b,t) row
    int total_threads = B_BATCH * nv;                    // B * nv

    const int smem_bytes = CHUNK * BLOCK * (int)sizeof(float4);  // 32 KB

    cudaFuncSetAttribute(lif_scan_kernel,
                         cudaFuncAttributeMaxDynamicSharedMemorySize, smem_bytes);

    int grid = (total_threads + BLOCK - 1) / BLOCK;

    lif_scan_kernel<<<grid, BLOCK, smem_bytes>>>(
        (const float4*)x, tau, (float4*)d_out, nv, total_threads);
}

// round 15
// speedup vs baseline: 1.0111x; 1.0111x over previous
#include <cuda_runtime.h>
#include <cuda_bf16.h>

// LIF neuron scan:
//   u[t] = tau * u[t-1] + x[t];  o[t] = (u[t] > 1);  u[t] *= (1 - o[t])
// x: [B, T, N] fp32, out: [B, T, N] fp32.  B=32, T=32, N=65536.
//
// R14: hybrid LDG + cp.async split. Chunk 0 = 16-deep LDG register burst
// (R6 pattern); chunk 1 = 16-deep cp.async group into 32KB smem. Both fired
// up front -> all 32 loads outstanding (same as R11, our best at 84.4us),
// but footprint halves on both axes: smem 64->32KB, regs ~154->~95 (chunk 1
// holds ZERO registers in flight). __launch_bounds__(128,4) -> 4 blocks/SM
// = 16 warps (R6's best-measured warp count) vs R11's 12, at identical
// burst/in-flight structure. Store runs stay pure 16-deep STG bursts (R9);
// no __syncthreads (each thread consumes only its own cp.async data; R13's
// 8-deep groups regressed, so groups stay 16-deep).

#define T_STEPS 32
#define B_BATCH 32
#define CHUNK   16
#define BLOCK   128

__device__ __forceinline__ void cp_async16(void* smem_dst, const void* gsrc, bool pred) {
    unsigned saddr = (unsigned)__cvta_generic_to_shared(smem_dst);
    if (pred)
        asm volatile("cp.async.cg.shared.global [%0], [%1], 16;\n"
                     :: "r"(saddr), "l"(gsrc));
}
__device__ __forceinline__ void cp_commit() {
    asm volatile("cp.async.commit_group;\n" ::: "memory");
}
template <int N>
__device__ __forceinline__ void cp_wait() {
    asm volatile("cp.async.wait_group %0;\n" :: "n"(N) : "memory");
}

__global__ __launch_bounds__(BLOCK, 4) void lif_scan_kernel(
    const float4* __restrict__ x,
    const float*  __restrict__ tau_p,
    float4*       __restrict__ out,
    int nv,          // N/4 (float4 lanes per (b,t) row)
    int total)       // B * nv
{
    extern __shared__ float4 sbuf[];   // [CHUNK][BLOCK] = 32 KB

    int tid = threadIdx.x;
    int i   = blockIdx.x * BLOCK + tid;
    bool active = (i < total);
    int  ii = active ? i : 0;

    // clamp learned decay to [0,1]
    float tau = __ldg(tau_p);
    tau = fminf(fmaxf(tau, 0.0f), 1.0f);

    int b = ii / nv;                   // nv is a power of two; compiler -> shift
    int j = ii - b * nv;

    size_t base = (size_t)b * T_STEPS * nv + j;
    const float4* xb = x   + base;
    float4*       ob = out + base;

    const size_t half = (size_t)CHUNK * nv;

    // ---- chunk 0: 16-deep LDG register burst ----
    float4 bufA[CHUNK];
#pragma unroll
    for (int t = 0; t < CHUNK; t++)
        bufA[t] = active ? __ldcs(&xb[(size_t)t * nv])
                         : make_float4(0.f, 0.f, 0.f, 0.f);

    // ---- chunk 1: 16-deep cp.async group (zero registers in flight) ----
#pragma unroll
    for (int t = 0; t < CHUNK; t++)
        cp_async16(&sbuf[t * BLOCK + tid], &xb[half + (size_t)t * nv], active);
    cp_commit();

    float ux = 0.0f, uy = 0.0f, uz = 0.0f, uw = 0.0f;

    // ---- compute A (overwrite bufA with outputs; chunk 1 in flight) ----
#pragma unroll
    for (int t = 0; t < CHUNK; t++) {
        float4 xi = bufA[t];

        ux = fmaf(tau, ux, xi.x);
        uy = fmaf(tau, uy, xi.y);
        uz = fmaf(tau, uz, xi.z);
        uw = fmaf(tau, uw, xi.w);

        float4 o;
        o.x = (ux > 1.0f) ? 1.0f : 0.0f;
        o.y = (uy > 1.0f) ? 1.0f : 0.0f;
        o.z = (uz > 1.0f) ? 1.0f : 0.0f;
        o.w = (uw > 1.0f) ? 1.0f : 0.0f;

        ux = (ux > 1.0f) ? 0.0f : ux;
        uy = (uy > 1.0f) ? 0.0f : uy;
        uz = (uz > 1.0f) ? 0.0f : uz;
        uw = (uw > 1.0f) ? 0.0f : uw;

        bufA[t] = o;
    }

    // ---- store run A: 16 back-to-back streaming stores ----
    if (active) {
#pragma unroll
        for (int t = 0; t < CHUNK; t++)
            __stcs(&ob[(size_t)t * nv], bufA[t]);
    }

    // ---- chunk 1 landed; compute B from smem into bufA ----
    cp_wait<0>();

#pragma unroll
    for (int t = 0; t < CHUNK; t++) {
        float4 xi = sbuf[t * BLOCK + tid];

        ux = fmaf(tau, ux, xi.x);
        uy = fmaf(tau, uy, xi.y);
        uz = fmaf(tau, uz, xi.z);
        uw = fmaf(tau, uw, xi.w);

        float4 o;
        o.x = (ux > 1.0f) ? 1.0f : 0.0f;
        o.y = (uy > 1.0f) ? 1.0f : 0.0f;
        o.z = (uz > 1.0f) ? 1.0f : 0.0f;
        o.w = (uw > 1.0f) ? 1.0f : 0.0f;

        ux = (ux > 1.0f) ? 0.0f : ux;
        uy = (uy > 1.0f) ? 0.0f : uy;
        uz = (uz > 1.0f) ? 0.0f : uz;
        uw = (uw > 1.0f) ? 0.0f : uw;

        bufA[t] = o;
    }

    // ---- store run B: 16 back-to-back streaming stores ----
    if (active) {
#pragma unroll
        for (int t = 0; t < CHUNK; t++)
            __stcs(&ob[half + (size_t)t * nv], bufA[t]);
    }
}

extern "C" void kernel_launch(void* const* d_in, const int* in_sizes, int n_in,
                              void* d_out, int out_size)
{
    const float* x   = (const float*)d_in[0];   // [B, T, N] fp32
    const float* tau = (const float*)d_in[1];   // [1] fp32

    int total_elems = in_sizes[0];                       // B*T*N
    int N  = total_elems / (B_BATCH * T_STEPS);
    int nv = N / 4;                                      // float4 per (b,t) row
    int total_threads = B_BATCH * nv;                    // B * nv

    const int smem_bytes = CHUNK * BLOCK * (int)sizeof(float4);  // 32 KB

    cudaFuncSetAttribute(lif_scan_kernel,
                         cudaFuncAttributeMaxDynamicSharedMemorySize, smem_bytes);

    int grid = (total_threads + BLOCK - 1) / BLOCK;

    lif_scan_kernel<<<grid, BLOCK, smem_bytes>>>(
        (const float4*)x, tau, (float4*)d_out, nv, total_threads);
}

// round 16
// speedup vs baseline: 1.0381x; 1.0267x over previous
#include <cuda_runtime.h>
#include <cuda_bf16.h>

// LIF neuron scan:
//   u[t] = tau * u[t-1] + x[t];  o[t] = (u[t] > 1);  u[t] *= (1 - o[t])
// x: [B, T, N] fp32, out: [B, T, N] fp32.  B=32, T=32, N=65536.
//
// R16: R6's LDG-16 burst kernel (best measured HBM: 6242 GB/s, regs=122,
// 14 warps/SM) + register-free L2 prefetch of chunk 1. After issuing chunk
// 0's 16-deep LDG burst, issue 16 prefetch.global.L2 for chunk 1 addresses.
// Prefetches hold no register and no scoreboard entry, so occupancy stays
// at R6's healthy point, but during compute A's serial-scan window (where
// R6 warps went memory-silent) DRAM->L2 fetches for chunk 1 proceed; chunk
// 1's LDG burst then completes at L2 latency (~234cyc) instead of DRAM
// (~577). Continuous read coverage (R11's win) without smem/occupancy cost
// (R11) or the LDG-behind-cp.async queue hazard (R14: prefetches have no
// consumer). Store runs stay pure back-to-back STG.128 (R9).

#define T_STEPS 32
#define B_BATCH 32
#define CHUNK   16

__device__ __forceinline__ void prefetch_l2(const void* p) {
    asm volatile("prefetch.global.L2 [%0];" :: "l"(p));
}

__global__ __launch_bounds__(128) void lif_scan_kernel(
    const float4* __restrict__ x,
    const float*  __restrict__ tau_p,
    float4*       __restrict__ out,
    int nv,          // N/4 (float4 lanes per (b,t) row)
    int total)       // B * nv
{
    int i = blockIdx.x * blockDim.x + threadIdx.x;
    if (i >= total) return;

    // clamp learned decay to [0,1]
    float tau = __ldg(tau_p);
    tau = fminf(fmaxf(tau, 0.0f), 1.0f);

    int b = i / nv;          // nv is a power of two; compiler -> shift
    int j = i - b * nv;

    size_t base = (size_t)b * T_STEPS * nv + j;
    const float4* xb = x   + base;
    float4*       ob = out + base;

    const size_t half = (size_t)CHUNK * nv;

    float ux = 0.0f, uy = 0.0f, uz = 0.0f, uw = 0.0f;

    // ================= chunk 0 =================
    // ---- read run: 16 independent 16B loads, back-to-back ----
    float4 buf[CHUNK];
#pragma unroll
    for (int t = 0; t < CHUNK; t++)
        buf[t] = __ldcs(&xb[(size_t)t * nv]);

    // ---- register-free L2 prefetch of chunk 1 (covers compute A window) ----
#pragma unroll
    for (int t = 0; t < CHUNK; t++)
        prefetch_l2(&xb[half + (size_t)t * nv]);

    // ---- compute A: sequential scan, outputs overwrite buf ----
#pragma unroll
    for (int t = 0; t < CHUNK; t++) {
        float4 xi = buf[t];

        ux = fmaf(tau, ux, xi.x);
        uy = fmaf(tau, uy, xi.y);
        uz = fmaf(tau, uz, xi.z);
        uw = fmaf(tau, uw, xi.w);

        float4 o;
        o.x = (ux > 1.0f) ? 1.0f : 0.0f;
        o.y = (uy > 1.0f) ? 1.0f : 0.0f;
        o.z = (uz > 1.0f) ? 1.0f : 0.0f;
        o.w = (uw > 1.0f) ? 1.0f : 0.0f;

        ux = (ux > 1.0f) ? 0.0f : ux;
        uy = (uy > 1.0f) ? 0.0f : uy;
        uz = (uz > 1.0f) ? 0.0f : uz;
        uw = (uw > 1.0f) ? 0.0f : uw;

        buf[t] = o;
    }

    // ---- store run A: 16 back-to-back streaming stores ----
#pragma unroll
    for (int t = 0; t < CHUNK; t++)
        __stcs(&ob[(size_t)t * nv], buf[t]);

    // ================= chunk 1 =================
    // ---- read run: 16 loads, mostly L2 hits thanks to the prefetch ----
#pragma unroll
    for (int t = 0; t < CHUNK; t++)
        buf[t] = __ldcs(&xb[half + (size_t)t * nv]);

    // ---- compute B ----
#pragma unroll
    for (int t = 0; t < CHUNK; t++) {
        float4 xi = buf[t];

        ux = fmaf(tau, ux, xi.x);
        uy = fmaf(tau, uy, xi.y);
        uz = fmaf(tau, uz, xi.z);
        uw = fmaf(tau, uw, xi.w);

        float4 o;
        o.x = (ux > 1.0f) ? 1.0f : 0.0f;
        o.y = (uy > 1.0f) ? 1.0f : 0.0f;
        o.z = (uz > 1.0f) ? 1.0f : 0.0f;
        o.w = (uw > 1.0f) ? 1.0f : 0.0f;

        ux = (ux > 1.0f) ? 0.0f : ux;
        uy = (uy > 1.0f) ? 0.0f : uy;
        uz = (uz > 1.0f) ? 0.0f : uz;
        uw = (uw > 1.0f) ? 0.0f : uw;

        buf[t] = o;
    }

    // ---- store run B: 16 back-to-back streaming stores ----
#pragma unroll
    for (int t = 0; t < CHUNK; t++)
        __stcs(&ob[half + (size_t)t * nv], buf[t]);
}

extern "C" void kernel_launch(void* const* d_in, const int* in_sizes, int n_in,
                              void* d_out, int out_size)
{
    const float* x   = (const float*)d_in[0];   // [B, T, N] fp32
    const float* tau = (const float*)d_in[1];   // [1] fp32

    int total_elems = in_sizes[0];                       // B*T*N
    int N  = total_elems / (B_BATCH * T_STEPS);
    int nv = N / 4;                                      // float4 per (b,t) row
    int total_threads = B_BATCH * nv;                    // B * nv

    int block = 128;
    int grid  = (total_threads + block - 1) / block;

    lif_scan_kernel<<<grid, block>>>(
        (const float4*)x, tau, (float4*)d_out, nv, total_threads);
}